// round 8
// baseline (speedup 1.0000x reference)
#include <cuda_runtime.h>
#include <stdint.h>

typedef unsigned long long ull;

#define NMAX   100000
#define EMAX   1600000
#define DIN    128
#define DOUT   32
#define CAP    64        // per-node source bucket capacity (deg ~ Poisson(16))
#define BM     128
#define BK     32
#define XPAD   (BK + 2)  // 34 floats: 8B-aligned rows, 4-distinct-bank pair loads

// ---- scratch (no allocations allowed) ----
__device__ float g_h[NMAX * DOUT];        // (x @ W) * dinv[row]  (pre-scaled)
__device__ float g_dinv[NMAX];            // (deg)^{-1/2}, deg = in-edges + 1
__device__ int   g_fill[NMAX + 1];        // [0..NMAX): in-degree; [NMAX]: ovf count
__device__ int   g_srcs[NMAX * CAP];      // bucketed sources per dst
__device__ int   g_ovf[2 * EMAX];         // overflow (src,dst) pairs

__device__ __forceinline__ void fma2(ull& acc, ull a, ull b) {
    asm("fma.rn.f32x2 %0, %1, %2, %0;" : "+l"(acc) : "l"(a), "l"(b));
}
__device__ __forceinline__ float unpack_sum(ull v) {
    float lo, hi;
    asm("mov.b64 {%0, %1}, %2;" : "=f"(lo), "=f"(hi) : "l"(v));
    return lo + hi;
}

// ---------------------------------------------------------------------------
// Bucket placement. Each block detects the edge dtype itself: for int64
// (little-endian, values < 2^31) every odd 32-bit word is 0; 256 samples of
// random int32 edge values are all-zero with prob ~1e-1280.
// ---------------------------------------------------------------------------
__global__ void k_place(const void* __restrict__ ei, int E) {
    __shared__ int s_is64;
    if (threadIdx.x == 0) s_is64 = 1;
    __syncthreads();
    if (((const unsigned*)ei)[2 * threadIdx.x + 1] != 0u) s_is64 = 0;
    __syncthreads();
    int is64 = s_is64;

    int e = blockIdx.x * blockDim.x + threadIdx.x;
    if (e >= E) return;
    int src, dst;
    if (is64) {
        src = (int)((const long long*)ei)[e];
        dst = (int)((const long long*)ei)[(long long)E + e];
    } else {
        src = ((const int*)ei)[e];
        dst = ((const int*)ei)[E + e];
    }
    int pos = atomicAdd(&g_fill[dst], 1);
    if (pos < CAP) {
        g_srcs[dst * CAP + pos] = src;
    } else {
        int o = atomicAdd(&g_fill[NMAX], 1);
        if (o < EMAX) { g_ovf[2 * o] = src; g_ovf[2 * o + 1] = dst; }
    }
}

// ---------------------------------------------------------------------------
// GEMM with packed f32x2 FMA (2x fp32 throughput on Blackwell):
// k-pairs live in lo/hi halves of 64-bit regs. W staged once in smem as
// float2 pairs ws2[k2][c] = {W[2k2][c], W[2k2+1][c]}; x chunk staged with
// 34-float row stride (8B-aligned, conflict-free 8B broadcast loads).
// 16 packed accumulators (4 rows x 4 cols); horizontal lo+hi at the end.
// Epilogue: g_h = acc*dinv, out = acc*dinv^2 + b (self-loop + bias).
// ---------------------------------------------------------------------------
__global__ void k_gemm(const float* __restrict__ x, const float* __restrict__ W,
                       const float* __restrict__ b, float* __restrict__ out, int n) {
    __shared__ float2 ws2[DIN / 2][DOUT];   // 16 KB
    __shared__ float  xs[BM][XPAD];         // 17.4 KB
    int t = threadIdx.x;
    int row0 = blockIdx.x * BM;
    int tx = t & 7, ty = t >> 3;

    // stage W pairs (coalesced: lanes sweep c)
#pragma unroll
    for (int it = 0; it < 8; it++) {
        int i = t + it * 256;              // i in [0, 2048)
        int k2 = i >> 5, c = i & 31;
        ws2[k2][c] = make_float2(W[(2 * k2) * DOUT + c], W[(2 * k2 + 1) * DOUT + c]);
    }

    ull acc2[4][4];
#pragma unroll
    for (int i = 0; i < 4; i++)
#pragma unroll
        for (int j = 0; j < 4; j++) acc2[i][j] = 0ull;   // {0.f, 0.f}

    for (int chunk = 0; chunk < 4; chunk++) {
        // stage x chunk: 128 rows x 8 float4, stored as float2 pairs (8B align)
#pragma unroll
        for (int it = 0; it < 4; it++) {
            int i = t + it * 256;
            int r = i >> 3, k4 = i & 7;
            int gr = row0 + r;
            float4 v = (gr < n)
                ? *(const float4*)&x[(size_t)gr * DIN + chunk * BK + k4 * 4]
                : make_float4(0.f, 0.f, 0.f, 0.f);
            *(float2*)&xs[r][k4 * 4]     = make_float2(v.x, v.y);
            *(float2*)&xs[r][k4 * 4 + 2] = make_float2(v.z, v.w);
        }
        __syncthreads();

#pragma unroll
        for (int k2l = 0; k2l < BK / 2; k2l++) {
            int k2 = chunk * (BK / 2) + k2l;
            ull a2[4], w2[4];
#pragma unroll
            for (int i = 0; i < 4; i++)
                a2[i] = *(const ull*)&xs[ty * 4 + i][2 * k2l];
#pragma unroll
            for (int j = 0; j < 4; j++)
                w2[j] = *(const ull*)&ws2[k2][tx * 4 + j];
#pragma unroll
            for (int i = 0; i < 4; i++)
#pragma unroll
                for (int j = 0; j < 4; j++)
                    fma2(acc2[i][j], a2[i], w2[j]);
        }
        __syncthreads();
    }

    float4 bb = *(const float4*)&b[tx * 4];
#pragma unroll
    for (int i = 0; i < 4; i++) {
        int row = row0 + ty * 4 + i;
        if (row >= n) break;
        float4 acc;
        acc.x = unpack_sum(acc2[i][0]);
        acc.y = unpack_sum(acc2[i][1]);
        acc.z = unpack_sum(acc2[i][2]);
        acc.w = unpack_sum(acc2[i][3]);
        float dinv = rsqrtf(1.0f + (float)g_fill[row]);
        if (tx == 0) g_dinv[row] = dinv;
        float4 hs;
        hs.x = acc.x * dinv; hs.y = acc.y * dinv;
        hs.z = acc.z * dinv; hs.w = acc.w * dinv;
        *(float4*)&g_h[row * DOUT + tx * 4] = hs;
        float4 o;
        o.x = fmaf(hs.x, dinv, bb.x);
        o.y = fmaf(hs.y, dinv, bb.y);
        o.z = fmaf(hs.z, dinv, bb.z);
        o.w = fmaf(hs.w, dinv, bb.w);
        *(float4*)&out[row * DOUT + tx * 4] = o;
    }
}

// ---------------------------------------------------------------------------
// Pull-side aggregation (speculative front batch) + fused overflow cleanup.
// Blocks [0, nb_agg): one warp per destination; srcs/cnt/dinv/out-row all
// issued in parallel (addresses depend only on d), 16 h-rows gathered
// speculatively (index clamped for safety) and accumulated under the cnt
// predicate; tail in 8-edge groups. Nodes with fill > CAP (normally none)
// use atomicAdd so the cleanup blocks can't race them.
// Blocks [nb_agg, nb_agg+16): scatter the overflow spill buffer atomically.
// ---------------------------------------------------------------------------
__device__ __forceinline__ int clampidx(int s) {
    return ((unsigned)s < (unsigned)NMAX) ? s : 0;
}

__global__ void __launch_bounds__(128) k_agg(float* __restrict__ out, int n, int nb_agg) {
    if (blockIdx.x >= nb_agg) {
        // ---- overflow cleanup (cold path) ----
        int cnt = g_fill[NMAX];
        if (cnt > EMAX) cnt = EMAX;
        int tid = (blockIdx.x - nb_agg) * 128 + threadIdx.x;
        for (int o = tid; o < cnt; o += 16 * 128) {
            int src = g_ovf[2 * o], dst = g_ovf[2 * o + 1];
            float nrm = g_dinv[dst];
            for (int c = 0; c < DOUT; c++)
                atomicAdd(&out[dst * DOUT + c], g_h[src * DOUT + c] * nrm);
        }
        return;
    }

    int warp = threadIdx.x >> 5, lane = threadIdx.x & 31;
    int d = blockIdx.x * 4 + warp;
    if (d >= n) return;

    int q  = lane >> 3;
    int c4 = lane & 7;

    const int* sr = &g_srcs[d * CAP];

    // --- parallel front batch ---
    int s0 = clampidx(sr[q]);
    int s1 = clampidx(sr[4 + q]);
    int s2 = clampidx(sr[8 + q]);
    int s3 = clampidx(sr[12 + q]);
    int cnt_raw = g_fill[d];
    float dd = g_dinv[d];
    float4* op = (float4*)&out[d * DOUT + c4 * 4];
    float4 oval = *op;

    // --- speculative h gathers ---
    float4 h0 = *(const float4*)&g_h[s0 * DOUT + c4 * 4];
    float4 h1 = *(const float4*)&g_h[s1 * DOUT + c4 * 4];
    float4 h2 = *(const float4*)&g_h[s2 * DOUT + c4 * 4];
    float4 h3 = *(const float4*)&g_h[s3 * DOUT + c4 * 4];

    int cnt = cnt_raw > CAP ? CAP : cnt_raw;

    float4 a0 = make_float4(0.f, 0.f, 0.f, 0.f);
    float4 a1 = make_float4(0.f, 0.f, 0.f, 0.f);
    if (q      < cnt) { a0.x += h0.x; a0.y += h0.y; a0.z += h0.z; a0.w += h0.w; }
    if (4 + q  < cnt) { a1.x += h1.x; a1.y += h1.y; a1.z += h1.z; a1.w += h1.w; }
    if (8 + q  < cnt) { a0.x += h2.x; a0.y += h2.y; a0.z += h2.z; a0.w += h2.w; }
    if (12 + q < cnt) { a1.x += h3.x; a1.y += h3.y; a1.z += h3.z; a1.w += h3.w; }

    for (int j = 16; j < cnt; j += 8) {
        int t0 = clampidx(sr[j + q]);
        int t1 = clampidx(sr[j + 4 + q]);
        float4 g0 = *(const float4*)&g_h[t0 * DOUT + c4 * 4];
        float4 g1 = *(const float4*)&g_h[t1 * DOUT + c4 * 4];
        if (j + q     < cnt) { a0.x += g0.x; a0.y += g0.y; a0.z += g0.z; a0.w += g0.w; }
        if (j + 4 + q < cnt) { a1.x += g1.x; a1.y += g1.y; a1.z += g1.z; a1.w += g1.w; }
    }

    a0.x += a1.x; a0.y += a1.y; a0.z += a1.z; a0.w += a1.w;

    a0.x += __shfl_xor_sync(0xffffffffu, a0.x, 8);
    a0.y += __shfl_xor_sync(0xffffffffu, a0.y, 8);
    a0.z += __shfl_xor_sync(0xffffffffu, a0.z, 8);
    a0.w += __shfl_xor_sync(0xffffffffu, a0.w, 8);
    a0.x += __shfl_xor_sync(0xffffffffu, a0.x, 16);
    a0.y += __shfl_xor_sync(0xffffffffu, a0.y, 16);
    a0.z += __shfl_xor_sync(0xffffffffu, a0.z, 16);
    a0.w += __shfl_xor_sync(0xffffffffu, a0.w, 16);

    if (lane < 8) {
        if (cnt_raw <= CAP) {
            oval.x = fmaf(a0.x, dd, oval.x);
            oval.y = fmaf(a0.y, dd, oval.y);
            oval.z = fmaf(a0.z, dd, oval.z);
            oval.w = fmaf(a0.w, dd, oval.w);
            *op = oval;
        } else {
            // overflow node: cleanup blocks also write here -> atomic
            float* os = (float*)op;
            atomicAdd(os + 0, a0.x * dd);
            atomicAdd(os + 1, a0.y * dd);
            atomicAdd(os + 2, a0.z * dd);
            atomicAdd(os + 3, a0.w * dd);
        }
    }
}

// ---------------------------------------------------------------------------
extern "C" void kernel_launch(void* const* d_in, const int* in_sizes, int n_in,
                              void* d_out, int out_size) {
    const float* x  = (const float*)d_in[0];
    const void*  ei = d_in[1];
    const float* W  = (const float*)d_in[2];
    const float* b  = (const float*)d_in[3];
    float* out = (float*)d_out;

    int n = in_sizes[0] / DIN;   // 100000
    int E = in_sizes[1] / 2;     // 1600000

    void* fill_ptr = nullptr;
    cudaGetSymbolAddress(&fill_ptr, g_fill);
    cudaMemsetAsync(fill_ptr, 0, (NMAX + 1) * sizeof(int), 0);

    k_place<<<(E + 255) / 256, 256>>>(ei, E);
    k_gemm<<<(n + BM - 1) / BM, 256>>>(x, W, b, out, n);

    int nb_agg = (n + 3) / 4;
    k_agg<<<nb_agg + 16, 128>>>(out, n, nb_agg);
}

// round 9
// speedup vs baseline: 1.0709x; 1.0709x over previous
#include <cuda_runtime.h>
#include <stdint.h>

#define NMAX   100000
#define EMAX   1600000
#define DIN    128
#define DOUT   32
#define CAP    64        // per-node source bucket capacity (deg ~ Poisson(16))
#define BM     128
#define BK     32

// ---- scratch (no allocations allowed) ----
__device__ float g_h[NMAX * DOUT];        // raw x@W, then scaled by k_scale
__device__ float g_dinv[NMAX];            // (deg)^{-1/2}, deg = in-edges + 1
__device__ int   g_fill[NMAX + 1];        // [0..NMAX): in-degree; [NMAX]: ovf count
__device__ int   g_srcs[NMAX * CAP];      // bucketed sources per dst
__device__ int   g_ovf[2 * EMAX];         // overflow (src,dst) pairs

// ---------------------------------------------------------------------------
// Fused placement + GEMM-mainloop. Every 9th block (b%9==8) is a GEMM block
// (matches the ~8:1 place:gemm block ratio), so L2-atomic-bound place blocks
// and FMA-bound gemm blocks coexist on each SM and overlap their idle pipes.
//
// Place role: bucket srcs[dst*CAP+slot]=src, count degree, spill overflow.
//   Dtype detection per block: int64 (LE, values < 2^31) => all odd 32-bit
//   words zero; 256 random int32 samples all-zero has prob ~1e-1280.
// Gemm role: 128x32 tile, BK=32, 256 threads, 4x4 micro-tile (R7-proven).
//   Writes RAW acc to g_h; dinv epilogue deferred to k_scale (g_fill not
//   ready while place blocks still run).
// ---------------------------------------------------------------------------
__global__ void __launch_bounds__(256) k_fused(
    const float* __restrict__ x, const float* __restrict__ W,
    const void* __restrict__ ei, int E, int n, int nPlace, int nGemm)
{
    __shared__ float xs[BM][BK + 1];   // 16.5 KB (gemm role)
    __shared__ float ws[BK][DOUT];     // 4 KB   (gemm role)
    __shared__ int   s_is64;           //         (place role)

    int b = blockIdx.x;
    int t = threadIdx.x;
    bool isGemm = ((b % 9) == 8) && (b / 9 < nGemm);

    if (!isGemm) {
        // ---------------- place role ----------------
        int pb = b - min((b + 1) / 9, nGemm);   // place block index
        if (pb >= nPlace) return;

        if (t == 0) s_is64 = 1;
        __syncthreads();
        if (((const unsigned*)ei)[2 * t + 1] != 0u) s_is64 = 0;
        __syncthreads();
        int is64 = s_is64;

        int e = pb * 256 + t;
        if (e >= E) return;
        int src, dst;
        if (is64) {
            src = (int)((const long long*)ei)[e];
            dst = (int)((const long long*)ei)[(long long)E + e];
        } else {
            src = ((const int*)ei)[e];
            dst = ((const int*)ei)[E + e];
        }
        int pos = atomicAdd(&g_fill[dst], 1);
        if (pos < CAP) {
            g_srcs[dst * CAP + pos] = src;
        } else {
            int o = atomicAdd(&g_fill[NMAX], 1);
            if (o < EMAX) { g_ovf[2 * o] = src; g_ovf[2 * o + 1] = dst; }
        }
        return;
    }

    // ---------------- gemm role ----------------
    int gb = b / 9;
    int row0 = gb * BM;
    int tx = t & 7, ty = t >> 3;

    float4 acc[4];
#pragma unroll
    for (int i = 0; i < 4; i++) acc[i] = make_float4(0.f, 0.f, 0.f, 0.f);

    for (int kc = 0; kc < DIN; kc += BK) {
#pragma unroll
        for (int it = 0; it < 4; it++) {
            int i = t + it * 256;
            int r = i >> 3, k4 = i & 7;
            int gr = row0 + r;
            float4 v = (gr < n)
                ? *(const float4*)&x[(size_t)gr * DIN + kc + k4 * 4]
                : make_float4(0.f, 0.f, 0.f, 0.f);
            xs[r][k4 * 4 + 0] = v.x;
            xs[r][k4 * 4 + 1] = v.y;
            xs[r][k4 * 4 + 2] = v.z;
            xs[r][k4 * 4 + 3] = v.w;
        }
        ((float4*)ws)[t] = ((const float4*)(W + kc * DOUT))[t];
        __syncthreads();

#pragma unroll
        for (int k = 0; k < BK; k++) {
            float a0 = xs[ty * 4 + 0][k];
            float a1 = xs[ty * 4 + 1][k];
            float a2 = xs[ty * 4 + 2][k];
            float a3 = xs[ty * 4 + 3][k];
            float4 bw = *(float4*)&ws[k][tx * 4];
            acc[0].x = fmaf(a0, bw.x, acc[0].x); acc[0].y = fmaf(a0, bw.y, acc[0].y);
            acc[0].z = fmaf(a0, bw.z, acc[0].z); acc[0].w = fmaf(a0, bw.w, acc[0].w);
            acc[1].x = fmaf(a1, bw.x, acc[1].x); acc[1].y = fmaf(a1, bw.y, acc[1].y);
            acc[1].z = fmaf(a1, bw.z, acc[1].z); acc[1].w = fmaf(a1, bw.w, acc[1].w);
            acc[2].x = fmaf(a2, bw.x, acc[2].x); acc[2].y = fmaf(a2, bw.y, acc[2].y);
            acc[2].z = fmaf(a2, bw.z, acc[2].z); acc[2].w = fmaf(a2, bw.w, acc[2].w);
            acc[3].x = fmaf(a3, bw.x, acc[3].x); acc[3].y = fmaf(a3, bw.y, acc[3].y);
            acc[3].z = fmaf(a3, bw.z, acc[3].z); acc[3].w = fmaf(a3, bw.w, acc[3].w);
        }
        __syncthreads();
    }

#pragma unroll
    for (int i = 0; i < 4; i++) {
        int row = row0 + ty * 4 + i;
        if (row >= n) break;
        *(float4*)&g_h[row * DOUT + tx * 4] = acc[i];   // raw acc
    }
}

// ---------------------------------------------------------------------------
// Epilogue: dinv = rsqrt(1+deg); g_h *= dinv; out = g_h*dinv + b
// (= acc*dinv^2 + b : self-loop + bias). Thread = (row, c4).
// ---------------------------------------------------------------------------
__global__ void k_scale(const float* __restrict__ b, float* __restrict__ out, int n) {
    int tid = blockIdx.x * 256 + threadIdx.x;
    int row = tid >> 3, c4 = tid & 7;
    if (row >= n) return;
    float dinv = rsqrtf(1.0f + (float)g_fill[row]);
    if (c4 == 0) g_dinv[row] = dinv;
    float4 a = *(float4*)&g_h[row * DOUT + c4 * 4];
    float4 hs = make_float4(a.x * dinv, a.y * dinv, a.z * dinv, a.w * dinv);
    *(float4*)&g_h[row * DOUT + c4 * 4] = hs;
    float4 bb = *(const float4*)&b[c4 * 4];
    float4 o;
    o.x = fmaf(hs.x, dinv, bb.x);
    o.y = fmaf(hs.y, dinv, bb.y);
    o.z = fmaf(hs.z, dinv, bb.z);
    o.w = fmaf(hs.w, dinv, bb.w);
    *(float4*)&out[row * DOUT + c4 * 4] = o;
}

// ---------------------------------------------------------------------------
// Pull-side aggregation (speculative front batch) + fused overflow cleanup.
// ---------------------------------------------------------------------------
__device__ __forceinline__ int clampidx(int s) {
    return ((unsigned)s < (unsigned)NMAX) ? s : 0;
}

__global__ void __launch_bounds__(128) k_agg(float* __restrict__ out, int n, int nb_agg) {
    if (blockIdx.x >= nb_agg) {
        // ---- overflow cleanup (cold path, normally 0 iterations) ----
        int cnt = g_fill[NMAX];
        if (cnt > EMAX) cnt = EMAX;
        int tid = (blockIdx.x - nb_agg) * 128 + threadIdx.x;
        for (int o = tid; o < cnt; o += 16 * 128) {
            int src = g_ovf[2 * o], dst = g_ovf[2 * o + 1];
            float nrm = g_dinv[dst];
            for (int c = 0; c < DOUT; c++)
                atomicAdd(&out[dst * DOUT + c], g_h[src * DOUT + c] * nrm);
        }
        return;
    }

    int warp = threadIdx.x >> 5, lane = threadIdx.x & 31;
    int d = blockIdx.x * 4 + warp;
    if (d >= n) return;

    int q  = lane >> 3;
    int c4 = lane & 7;

    const int* sr = &g_srcs[d * CAP];

    // --- parallel front batch (all addresses depend only on d) ---
    int s0 = clampidx(sr[q]);
    int s1 = clampidx(sr[4 + q]);
    int s2 = clampidx(sr[8 + q]);
    int s3 = clampidx(sr[12 + q]);
    int cnt_raw = g_fill[d];
    float dd = g_dinv[d];
    float4* op = (float4*)&out[d * DOUT + c4 * 4];
    float4 oval = *op;

    // --- speculative h gathers ---
    float4 h0 = *(const float4*)&g_h[s0 * DOUT + c4 * 4];
    float4 h1 = *(const float4*)&g_h[s1 * DOUT + c4 * 4];
    float4 h2 = *(const float4*)&g_h[s2 * DOUT + c4 * 4];
    float4 h3 = *(const float4*)&g_h[s3 * DOUT + c4 * 4];

    int cnt = cnt_raw > CAP ? CAP : cnt_raw;

    float4 a0 = make_float4(0.f, 0.f, 0.f, 0.f);
    float4 a1 = make_float4(0.f, 0.f, 0.f, 0.f);
    if (q      < cnt) { a0.x += h0.x; a0.y += h0.y; a0.z += h0.z; a0.w += h0.w; }
    if (4 + q  < cnt) { a1.x += h1.x; a1.y += h1.y; a1.z += h1.z; a1.w += h1.w; }
    if (8 + q  < cnt) { a0.x += h2.x; a0.y += h2.y; a0.z += h2.z; a0.w += h2.w; }
    if (12 + q < cnt) { a1.x += h3.x; a1.y += h3.y; a1.z += h3.z; a1.w += h3.w; }

    for (int j = 16; j < cnt; j += 8) {
        int t0 = clampidx(sr[j + q]);
        int t1 = clampidx(sr[j + 4 + q]);
        float4 g0 = *(const float4*)&g_h[t0 * DOUT + c4 * 4];
        float4 g1 = *(const float4*)&g_h[t1 * DOUT + c4 * 4];
        if (j + q     < cnt) { a0.x += g0.x; a0.y += g0.y; a0.z += g0.z; a0.w += g0.w; }
        if (j + 4 + q < cnt) { a1.x += g1.x; a1.y += g1.y; a1.z += g1.z; a1.w += g1.w; }
    }

    a0.x += a1.x; a0.y += a1.y; a0.z += a1.z; a0.w += a1.w;

    a0.x += __shfl_xor_sync(0xffffffffu, a0.x, 8);
    a0.y += __shfl_xor_sync(0xffffffffu, a0.y, 8);
    a0.z += __shfl_xor_sync(0xffffffffu, a0.z, 8);
    a0.w += __shfl_xor_sync(0xffffffffu, a0.w, 8);
    a0.x += __shfl_xor_sync(0xffffffffu, a0.x, 16);
    a0.y += __shfl_xor_sync(0xffffffffu, a0.y, 16);
    a0.z += __shfl_xor_sync(0xffffffffu, a0.z, 16);
    a0.w += __shfl_xor_sync(0xffffffffu, a0.w, 16);

    if (lane < 8) {
        if (cnt_raw <= CAP) {
            oval.x = fmaf(a0.x, dd, oval.x);
            oval.y = fmaf(a0.y, dd, oval.y);
            oval.z = fmaf(a0.z, dd, oval.z);
            oval.w = fmaf(a0.w, dd, oval.w);
            *op = oval;
        } else {
            float* os = (float*)op;
            atomicAdd(os + 0, a0.x * dd);
            atomicAdd(os + 1, a0.y * dd);
            atomicAdd(os + 2, a0.z * dd);
            atomicAdd(os + 3, a0.w * dd);
        }
    }
}

// ---------------------------------------------------------------------------
extern "C" void kernel_launch(void* const* d_in, const int* in_sizes, int n_in,
                              void* d_out, int out_size) {
    const float* x  = (const float*)d_in[0];
    const void*  ei = d_in[1];
    const float* W  = (const float*)d_in[2];
    const float* b  = (const float*)d_in[3];
    float* out = (float*)d_out;

    int n = in_sizes[0] / DIN;   // 100000
    int E = in_sizes[1] / 2;     // 1600000

    void* fill_ptr = nullptr;
    cudaGetSymbolAddress(&fill_ptr, g_fill);
    cudaMemsetAsync(fill_ptr, 0, (NMAX + 1) * sizeof(int), 0);

    int nPlace = (E + 255) / 256;             // 6250
    int nGemm  = (n + BM - 1) / BM;           // 782
    int grid   = nPlace + nGemm;              // 7032
    if (grid < 9 * nGemm) grid = 9 * nGemm;   // ensure all gemm slots exist (7038)

    k_fused<<<grid, 256>>>(x, W, ei, E, n, nPlace, nGemm);
    k_scale<<<(n * 8 + 255) / 256, 256>>>(b, out, n);

    int nb_agg = (n + 3) / 4;
    k_agg<<<nb_agg + 16, 128>>>(out, n, nb_agg);
}

// round 10
// speedup vs baseline: 1.1266x; 1.0520x over previous
#include <cuda_runtime.h>
#include <stdint.h>

#define NMAX   100000
#define EMAX   1600000
#define DIN    128
#define DOUT   32
#define CAP    64        // per-node source bucket capacity (deg ~ Poisson(16))
#define BM     128
#define BK     32

// ---- scratch (no allocations allowed) ----
__device__ float g_h[NMAX * DOUT];        // (x @ W) * dinv[row]  (pre-scaled)
__device__ float g_dinv[NMAX];            // (deg)^{-1/2}, deg = in-edges + 1
__device__ int   g_fill[NMAX + 1];        // [0..NMAX): in-degree; [NMAX]: ovf count
__device__ int   g_srcs[NMAX * CAP];      // bucketed sources per dst
__device__ int   g_ovf[2 * EMAX];         // overflow (src,dst) pairs

// ---------------------------------------------------------------------------
// Bucket placement, 4 edges per thread with front-batched loads:
// all 8 edge-index loads issue together, then 4 INDEPENDENT atomicAdds are
// in flight at once (the R8 version had MLP=1 on the ~318-cyc ATOMG round
// trip and sat at 10% issue). Dtype detection per block: int64 (LE, values
// < 2^31) => all odd 32-bit words zero; 256 random int32 samples all-zero
// has prob ~1e-1280.
// ---------------------------------------------------------------------------
__global__ void __launch_bounds__(256) k_place(const void* __restrict__ ei, int E) {
    __shared__ int s_is64;
    if (threadIdx.x == 0) s_is64 = 1;
    __syncthreads();
    if (((const unsigned*)ei)[2 * threadIdx.x + 1] != 0u) s_is64 = 0;
    __syncthreads();
    int is64 = s_is64;

    int base = blockIdx.x * 1024 + threadIdx.x;
    int e[4];
    int src[4], dst[4];
#pragma unroll
    for (int i = 0; i < 4; i++) e[i] = base + i * 256;

    // front-batched loads (predicated, all independent)
    if (is64) {
        const long long* p = (const long long*)ei;
#pragma unroll
        for (int i = 0; i < 4; i++)
            if (e[i] < E) { src[i] = (int)p[e[i]]; dst[i] = (int)p[(long long)E + e[i]]; }
    } else {
        const int* p = (const int*)ei;
#pragma unroll
        for (int i = 0; i < 4; i++)
            if (e[i] < E) { src[i] = p[e[i]]; dst[i] = p[E + e[i]]; }
    }

    // 4 independent atomics in flight
    int pos[4];
#pragma unroll
    for (int i = 0; i < 4; i++)
        if (e[i] < E) pos[i] = atomicAdd(&g_fill[dst[i]], 1);

#pragma unroll
    for (int i = 0; i < 4; i++) {
        if (e[i] >= E) continue;
        if (pos[i] < CAP) {
            g_srcs[dst[i] * CAP + pos[i]] = src[i];
        } else {
            int o = atomicAdd(&g_fill[NMAX], 1);
            if (o < EMAX) { g_ovf[2 * o] = src[i]; g_ovf[2 * o + 1] = dst[i]; }
        }
    }
}

// ---------------------------------------------------------------------------
// GEMM (R7-proven): 128x32 tile, BK=32, 256 threads, 4x4 micro-tile.
// Epilogue: dinv = rsqrt(1+deg); g_h = acc*dinv (source-side norm folded);
// out = acc*dinv^2 + b (self-loop + bias).
// ---------------------------------------------------------------------------
__global__ void k_gemm(const float* __restrict__ x, const float* __restrict__ W,
                       const float* __restrict__ b, float* __restrict__ out, int n) {
    __shared__ float xs[BM][BK + 1];   // 16.5 KB
    __shared__ float ws[BK][DOUT];     // 4 KB
    int t = threadIdx.x;
    int row0 = blockIdx.x * BM;
    int tx = t & 7, ty = t >> 3;

    float4 acc[4];
#pragma unroll
    for (int i = 0; i < 4; i++) acc[i] = make_float4(0.f, 0.f, 0.f, 0.f);

    for (int kc = 0; kc < DIN; kc += BK) {
#pragma unroll
        for (int it = 0; it < 4; it++) {
            int i = t + it * 256;
            int r = i >> 3, k4 = i & 7;
            int gr = row0 + r;
            float4 v = (gr < n)
                ? *(const float4*)&x[(size_t)gr * DIN + kc + k4 * 4]
                : make_float4(0.f, 0.f, 0.f, 0.f);
            xs[r][k4 * 4 + 0] = v.x;
            xs[r][k4 * 4 + 1] = v.y;
            xs[r][k4 * 4 + 2] = v.z;
            xs[r][k4 * 4 + 3] = v.w;
        }
        ((float4*)ws)[t] = ((const float4*)(W + kc * DOUT))[t];
        __syncthreads();

#pragma unroll
        for (int k = 0; k < BK; k++) {
            float a0 = xs[ty * 4 + 0][k];
            float a1 = xs[ty * 4 + 1][k];
            float a2 = xs[ty * 4 + 2][k];
            float a3 = xs[ty * 4 + 3][k];
            float4 bw = *(float4*)&ws[k][tx * 4];
            acc[0].x = fmaf(a0, bw.x, acc[0].x); acc[0].y = fmaf(a0, bw.y, acc[0].y);
            acc[0].z = fmaf(a0, bw.z, acc[0].z); acc[0].w = fmaf(a0, bw.w, acc[0].w);
            acc[1].x = fmaf(a1, bw.x, acc[1].x); acc[1].y = fmaf(a1, bw.y, acc[1].y);
            acc[1].z = fmaf(a1, bw.z, acc[1].z); acc[1].w = fmaf(a1, bw.w, acc[1].w);
            acc[2].x = fmaf(a2, bw.x, acc[2].x); acc[2].y = fmaf(a2, bw.y, acc[2].y);
            acc[2].z = fmaf(a2, bw.z, acc[2].z); acc[2].w = fmaf(a2, bw.w, acc[2].w);
            acc[3].x = fmaf(a3, bw.x, acc[3].x); acc[3].y = fmaf(a3, bw.y, acc[3].y);
            acc[3].z = fmaf(a3, bw.z, acc[3].z); acc[3].w = fmaf(a3, bw.w, acc[3].w);
        }
        __syncthreads();
    }

    float4 bb = *(const float4*)&b[tx * 4];
#pragma unroll
    for (int i = 0; i < 4; i++) {
        int row = row0 + ty * 4 + i;
        if (row >= n) break;
        float dinv = rsqrtf(1.0f + (float)g_fill[row]);
        if (tx == 0) g_dinv[row] = dinv;
        float4 hs;
        hs.x = acc[i].x * dinv; hs.y = acc[i].y * dinv;
        hs.z = acc[i].z * dinv; hs.w = acc[i].w * dinv;
        *(float4*)&g_h[row * DOUT + tx * 4] = hs;
        float4 o;
        o.x = fmaf(hs.x, dinv, bb.x);
        o.y = fmaf(hs.y, dinv, bb.y);
        o.z = fmaf(hs.z, dinv, bb.z);
        o.w = fmaf(hs.w, dinv, bb.w);
        *(float4*)&out[row * DOUT + tx * 4] = o;
    }
}

// ---------------------------------------------------------------------------
// Pull-side aggregation (speculative front batch) + fused overflow cleanup.
// ---------------------------------------------------------------------------
__device__ __forceinline__ int clampidx(int s) {
    return ((unsigned)s < (unsigned)NMAX) ? s : 0;
}

__global__ void __launch_bounds__(128) k_agg(float* __restrict__ out, int n, int nb_agg) {
    if (blockIdx.x >= nb_agg) {
        // ---- overflow cleanup (cold path, normally 0 iterations) ----
        int cnt = g_fill[NMAX];
        if (cnt > EMAX) cnt = EMAX;
        int tid = (blockIdx.x - nb_agg) * 128 + threadIdx.x;
        for (int o = tid; o < cnt; o += 16 * 128) {
            int src = g_ovf[2 * o], dst = g_ovf[2 * o + 1];
            float nrm = g_dinv[dst];
            for (int c = 0; c < DOUT; c++)
                atomicAdd(&out[dst * DOUT + c], g_h[src * DOUT + c] * nrm);
        }
        return;
    }

    int warp = threadIdx.x >> 5, lane = threadIdx.x & 31;
    int d = blockIdx.x * 4 + warp;
    if (d >= n) return;

    int q  = lane >> 3;
    int c4 = lane & 7;

    const int* sr = &g_srcs[d * CAP];

    // --- parallel front batch (all addresses depend only on d) ---
    int s0 = clampidx(sr[q]);
    int s1 = clampidx(sr[4 + q]);
    int s2 = clampidx(sr[8 + q]);
    int s3 = clampidx(sr[12 + q]);
    int cnt_raw = g_fill[d];
    float dd = g_dinv[d];
    float4* op = (float4*)&out[d * DOUT + c4 * 4];
    float4 oval = *op;

    // --- speculative h gathers ---
    float4 h0 = *(const float4*)&g_h[s0 * DOUT + c4 * 4];
    float4 h1 = *(const float4*)&g_h[s1 * DOUT + c4 * 4];
    float4 h2 = *(const float4*)&g_h[s2 * DOUT + c4 * 4];
    float4 h3 = *(const float4*)&g_h[s3 * DOUT + c4 * 4];

    int cnt = cnt_raw > CAP ? CAP : cnt_raw;

    float4 a0 = make_float4(0.f, 0.f, 0.f, 0.f);
    float4 a1 = make_float4(0.f, 0.f, 0.f, 0.f);
    if (q      < cnt) { a0.x += h0.x; a0.y += h0.y; a0.z += h0.z; a0.w += h0.w; }
    if (4 + q  < cnt) { a1.x += h1.x; a1.y += h1.y; a1.z += h1.z; a1.w += h1.w; }
    if (8 + q  < cnt) { a0.x += h2.x; a0.y += h2.y; a0.z += h2.z; a0.w += h2.w; }
    if (12 + q < cnt) { a1.x += h3.x; a1.y += h3.y; a1.z += h3.z; a1.w += h3.w; }

    for (int j = 16; j < cnt; j += 8) {
        int t0 = clampidx(sr[j + q]);
        int t1 = clampidx(sr[j + 4 + q]);
        float4 g0 = *(const float4*)&g_h[t0 * DOUT + c4 * 4];
        float4 g1 = *(const float4*)&g_h[t1 * DOUT + c4 * 4];
        if (j + q     < cnt) { a0.x += g0.x; a0.y += g0.y; a0.z += g0.z; a0.w += g0.w; }
        if (j + 4 + q < cnt) { a1.x += g1.x; a1.y += g1.y; a1.z += g1.z; a1.w += g1.w; }
    }

    a0.x += a1.x; a0.y += a1.y; a0.z += a1.z; a0.w += a1.w;

    a0.x += __shfl_xor_sync(0xffffffffu, a0.x, 8);
    a0.y += __shfl_xor_sync(0xffffffffu, a0.y, 8);
    a0.z += __shfl_xor_sync(0xffffffffu, a0.z, 8);
    a0.w += __shfl_xor_sync(0xffffffffu, a0.w, 8);
    a0.x += __shfl_xor_sync(0xffffffffu, a0.x, 16);
    a0.y += __shfl_xor_sync(0xffffffffu, a0.y, 16);
    a0.z += __shfl_xor_sync(0xffffffffu, a0.z, 16);
    a0.w += __shfl_xor_sync(0xffffffffu, a0.w, 16);

    if (lane < 8) {
        if (cnt_raw <= CAP) {
            oval.x = fmaf(a0.x, dd, oval.x);
            oval.y = fmaf(a0.y, dd, oval.y);
            oval.z = fmaf(a0.z, dd, oval.z);
            oval.w = fmaf(a0.w, dd, oval.w);
            *op = oval;
        } else {
            float* os = (float*)op;
            atomicAdd(os + 0, a0.x * dd);
            atomicAdd(os + 1, a0.y * dd);
            atomicAdd(os + 2, a0.z * dd);
            atomicAdd(os + 3, a0.w * dd);
        }
    }
}

// ---------------------------------------------------------------------------
extern "C" void kernel_launch(void* const* d_in, const int* in_sizes, int n_in,
                              void* d_out, int out_size) {
    const float* x  = (const float*)d_in[0];
    const void*  ei = d_in[1];
    const float* W  = (const float*)d_in[2];
    const float* b  = (const float*)d_in[3];
    float* out = (float*)d_out;

    int n = in_sizes[0] / DIN;   // 100000
    int E = in_sizes[1] / 2;     // 1600000

    void* fill_ptr = nullptr;
    cudaGetSymbolAddress(&fill_ptr, g_fill);
    cudaMemsetAsync(fill_ptr, 0, (NMAX + 1) * sizeof(int), 0);

    k_place<<<(E + 1023) / 1024, 256>>>(ei, E);
    k_gemm<<<(n + BM - 1) / BM, 256>>>(x, W, b, out, n);

    int nb_agg = (n + 3) / 4;
    k_agg<<<nb_agg + 16, 128>>>(out, n, nb_agg);
}

// round 11
// speedup vs baseline: 1.1859x; 1.0526x over previous
#include <cuda_runtime.h>
#include <stdint.h>

#define NMAX   100000
#define EMAX   1600000
#define DIN    128
#define DOUT   32
#define CAP    64        // per-node source bucket capacity (deg ~ Poisson(16))
#define BM     128
#define BK     32

// ---- scratch (no allocations allowed) ----
__device__ float g_h[NMAX * DOUT];        // raw x@W, scaled in k_scale
__device__ float g_dinv[NMAX];            // (deg)^{-1/2}, deg = in-edges + 1
__device__ int   g_fill[NMAX + 1];        // [0..NMAX): in-degree; [NMAX]: ovf count
__device__ int   g_srcs[NMAX * CAP];      // bucketed sources per dst
__device__ int   g_ovf[2 * EMAX];         // overflow (src,dst) pairs

// ---------------------------------------------------------------------------
// Bucket placement (R8 formulation — measured faster than 4-edge batching:
// the binder is L2-side atomic service, not SM-side MLP).
// Dtype detection per block: int64 (LE, values < 2^31) => all odd 32-bit
// words zero; 256 random int32 samples all-zero has prob ~1e-1280.
// ---------------------------------------------------------------------------
__global__ void k_place(const void* __restrict__ ei, int E) {
    __shared__ int s_is64;
    if (threadIdx.x == 0) s_is64 = 1;
    __syncthreads();
    if (((const unsigned*)ei)[2 * threadIdx.x + 1] != 0u) s_is64 = 0;
    __syncthreads();
    int is64 = s_is64;

    int e = blockIdx.x * blockDim.x + threadIdx.x;
    if (e >= E) return;
    int src, dst;
    if (is64) {
        src = (int)((const long long*)ei)[e];
        dst = (int)((const long long*)ei)[(long long)E + e];
    } else {
        src = ((const int*)ei)[e];
        dst = ((const int*)ei)[E + e];
    }
    int pos = atomicAdd(&g_fill[dst], 1);
    if (pos < CAP) {
        g_srcs[dst * CAP + pos] = src;
    } else {
        int o = atomicAdd(&g_fill[NMAX], 1);
        if (o < EMAX) { g_ovf[2 * o] = src; g_ovf[2 * o + 1] = dst; }
    }
}

// ---------------------------------------------------------------------------
// GEMM mainloop only (no g_fill dependency -> can run concurrently with
// k_place on a forked stream). 128x32 tile, BK=32, 4x4 micro-tile.
// Writes RAW acc to g_h; dinv epilogue in k_scale after the join.
// ---------------------------------------------------------------------------
__global__ void k_gemm(const float* __restrict__ x, const float* __restrict__ W,
                       int n) {
    __shared__ float xs[BM][BK + 1];   // 16.5 KB
    __shared__ float ws[BK][DOUT];     // 4 KB
    int t = threadIdx.x;
    int row0 = blockIdx.x * BM;
    int tx = t & 7, ty = t >> 3;

    float4 acc[4];
#pragma unroll
    for (int i = 0; i < 4; i++) acc[i] = make_float4(0.f, 0.f, 0.f, 0.f);

    for (int kc = 0; kc < DIN; kc += BK) {
#pragma unroll
        for (int it = 0; it < 4; it++) {
            int i = t + it * 256;
            int r = i >> 3, k4 = i & 7;
            int gr = row0 + r;
            float4 v = (gr < n)
                ? *(const float4*)&x[(size_t)gr * DIN + kc + k4 * 4]
                : make_float4(0.f, 0.f, 0.f, 0.f);
            xs[r][k4 * 4 + 0] = v.x;
            xs[r][k4 * 4 + 1] = v.y;
            xs[r][k4 * 4 + 2] = v.z;
            xs[r][k4 * 4 + 3] = v.w;
        }
        ((float4*)ws)[t] = ((const float4*)(W + kc * DOUT))[t];
        __syncthreads();

#pragma unroll
        for (int k = 0; k < BK; k++) {
            float a0 = xs[ty * 4 + 0][k];
            float a1 = xs[ty * 4 + 1][k];
            float a2 = xs[ty * 4 + 2][k];
            float a3 = xs[ty * 4 + 3][k];
            float4 bw = *(float4*)&ws[k][tx * 4];
            acc[0].x = fmaf(a0, bw.x, acc[0].x); acc[0].y = fmaf(a0, bw.y, acc[0].y);
            acc[0].z = fmaf(a0, bw.z, acc[0].z); acc[0].w = fmaf(a0, bw.w, acc[0].w);
            acc[1].x = fmaf(a1, bw.x, acc[1].x); acc[1].y = fmaf(a1, bw.y, acc[1].y);
            acc[1].z = fmaf(a1, bw.z, acc[1].z); acc[1].w = fmaf(a1, bw.w, acc[1].w);
            acc[2].x = fmaf(a2, bw.x, acc[2].x); acc[2].y = fmaf(a2, bw.y, acc[2].y);
            acc[2].z = fmaf(a2, bw.z, acc[2].z); acc[2].w = fmaf(a2, bw.w, acc[2].w);
            acc[3].x = fmaf(a3, bw.x, acc[3].x); acc[3].y = fmaf(a3, bw.y, acc[3].y);
            acc[3].z = fmaf(a3, bw.z, acc[3].z); acc[3].w = fmaf(a3, bw.w, acc[3].w);
        }
        __syncthreads();
    }

#pragma unroll
    for (int i = 0; i < 4; i++) {
        int row = row0 + ty * 4 + i;
        if (row >= n) break;
        *(float4*)&g_h[row * DOUT + tx * 4] = acc[i];
    }
}

// ---------------------------------------------------------------------------
// Join epilogue: dinv = rsqrt(1+deg); g_h *= dinv; out = g_h*dinv + b.
// ---------------------------------------------------------------------------
__global__ void k_scale(const float* __restrict__ b, float* __restrict__ out, int n) {
    int tid = blockIdx.x * 256 + threadIdx.x;
    int row = tid >> 3, c4 = tid & 7;
    if (row >= n) return;
    float dinv = rsqrtf(1.0f + (float)g_fill[row]);
    if (c4 == 0) g_dinv[row] = dinv;
    float4 a = *(float4*)&g_h[row * DOUT + c4 * 4];
    float4 hs = make_float4(a.x * dinv, a.y * dinv, a.z * dinv, a.w * dinv);
    *(float4*)&g_h[row * DOUT + c4 * 4] = hs;
    float4 bb = *(const float4*)&b[c4 * 4];
    float4 o;
    o.x = fmaf(hs.x, dinv, bb.x);
    o.y = fmaf(hs.y, dinv, bb.y);
    o.z = fmaf(hs.z, dinv, bb.z);
    o.w = fmaf(hs.w, dinv, bb.w);
    *(float4*)&out[row * DOUT + c4 * 4] = o;
}

// ---------------------------------------------------------------------------
// Pull-side aggregation (speculative front batch) + fused overflow cleanup.
// ---------------------------------------------------------------------------
__device__ __forceinline__ int clampidx(int s) {
    return ((unsigned)s < (unsigned)NMAX) ? s : 0;
}

__global__ void __launch_bounds__(128) k_agg(float* __restrict__ out, int n, int nb_agg) {
    if (blockIdx.x >= nb_agg) {
        int cnt = g_fill[NMAX];
        if (cnt > EMAX) cnt = EMAX;
        int tid = (blockIdx.x - nb_agg) * 128 + threadIdx.x;
        for (int o = tid; o < cnt; o += 16 * 128) {
            int src = g_ovf[2 * o], dst = g_ovf[2 * o + 1];
            float nrm = g_dinv[dst];
            for (int c = 0; c < DOUT; c++)
                atomicAdd(&out[dst * DOUT + c], g_h[src * DOUT + c] * nrm);
        }
        return;
    }

    int warp = threadIdx.x >> 5, lane = threadIdx.x & 31;
    int d = blockIdx.x * 4 + warp;
    if (d >= n) return;

    int q  = lane >> 3;
    int c4 = lane & 7;

    const int* sr = &g_srcs[d * CAP];

    // parallel front batch (addresses depend only on d)
    int s0 = clampidx(sr[q]);
    int s1 = clampidx(sr[4 + q]);
    int s2 = clampidx(sr[8 + q]);
    int s3 = clampidx(sr[12 + q]);
    int cnt_raw = g_fill[d];
    float dd = g_dinv[d];
    float4* op = (float4*)&out[d * DOUT + c4 * 4];
    float4 oval = *op;

    float4 h0 = *(const float4*)&g_h[s0 * DOUT + c4 * 4];
    float4 h1 = *(const float4*)&g_h[s1 * DOUT + c4 * 4];
    float4 h2 = *(const float4*)&g_h[s2 * DOUT + c4 * 4];
    float4 h3 = *(const float4*)&g_h[s3 * DOUT + c4 * 4];

    int cnt = cnt_raw > CAP ? CAP : cnt_raw;

    float4 a0 = make_float4(0.f, 0.f, 0.f, 0.f);
    float4 a1 = make_float4(0.f, 0.f, 0.f, 0.f);
    if (q      < cnt) { a0.x += h0.x; a0.y += h0.y; a0.z += h0.z; a0.w += h0.w; }
    if (4 + q  < cnt) { a1.x += h1.x; a1.y += h1.y; a1.z += h1.z; a1.w += h1.w; }
    if (8 + q  < cnt) { a0.x += h2.x; a0.y += h2.y; a0.z += h2.z; a0.w += h2.w; }
    if (12 + q < cnt) { a1.x += h3.x; a1.y += h3.y; a1.z += h3.z; a1.w += h3.w; }

    for (int j = 16; j < cnt; j += 8) {
        int t0 = clampidx(sr[j + q]);
        int t1 = clampidx(sr[j + 4 + q]);
        float4 g0 = *(const float4*)&g_h[t0 * DOUT + c4 * 4];
        float4 g1 = *(const float4*)&g_h[t1 * DOUT + c4 * 4];
        if (j + q     < cnt) { a0.x += g0.x; a0.y += g0.y; a0.z += g0.z; a0.w += g0.w; }
        if (j + 4 + q < cnt) { a1.x += g1.x; a1.y += g1.y; a1.z += g1.z; a1.w += g1.w; }
    }

    a0.x += a1.x; a0.y += a1.y; a0.z += a1.z; a0.w += a1.w;

    a0.x += __shfl_xor_sync(0xffffffffu, a0.x, 8);
    a0.y += __shfl_xor_sync(0xffffffffu, a0.y, 8);
    a0.z += __shfl_xor_sync(0xffffffffu, a0.z, 8);
    a0.w += __shfl_xor_sync(0xffffffffu, a0.w, 8);
    a0.x += __shfl_xor_sync(0xffffffffu, a0.x, 16);
    a0.y += __shfl_xor_sync(0xffffffffu, a0.y, 16);
    a0.z += __shfl_xor_sync(0xffffffffu, a0.z, 16);
    a0.w += __shfl_xor_sync(0xffffffffu, a0.w, 16);

    if (lane < 8) {
        if (cnt_raw <= CAP) {
            oval.x = fmaf(a0.x, dd, oval.x);
            oval.y = fmaf(a0.y, dd, oval.y);
            oval.z = fmaf(a0.z, dd, oval.z);
            oval.w = fmaf(a0.w, dd, oval.w);
            *op = oval;
        } else {
            float* os = (float*)op;
            atomicAdd(os + 0, a0.x * dd);
            atomicAdd(os + 1, a0.y * dd);
            atomicAdd(os + 2, a0.z * dd);
            atomicAdd(os + 3, a0.w * dd);
        }
    }
}

// ---------------------------------------------------------------------------
// Launch: fork place∥gemm onto two streams (captured as parallel graph
// branches), join, then scale + agg. Stream/events are created lazily on the
// FIRST call (the uncaptured correctness run), so no resource creation ever
// happens during graph capture; every call then does identical work.
// ---------------------------------------------------------------------------
extern "C" void kernel_launch(void* const* d_in, const int* in_sizes, int n_in,
                              void* d_out, int out_size) {
    const float* x  = (const float*)d_in[0];
    const void*  ei = d_in[1];
    const float* W  = (const float*)d_in[2];
    const float* b  = (const float*)d_in[3];
    float* out = (float*)d_out;

    int n = in_sizes[0] / DIN;   // 100000
    int E = in_sizes[1] / 2;     // 1600000

    static cudaStream_t s2 = nullptr;
    static cudaEvent_t evFork = nullptr, evJoin = nullptr;
    if (!s2) {
        cudaStreamCreateWithFlags(&s2, cudaStreamNonBlocking);
        cudaEventCreateWithFlags(&evFork, cudaEventDisableTiming);
        cudaEventCreateWithFlags(&evJoin, cudaEventDisableTiming);
    }

    void* fill_ptr = nullptr;
    cudaGetSymbolAddress(&fill_ptr, g_fill);

    // fork: gemm branch on s2 (independent of g_fill)
    cudaEventRecord(evFork, 0);
    cudaStreamWaitEvent(s2, evFork, 0);
    k_gemm<<<(n + BM - 1) / BM, 256, 0, s2>>>(x, W, n);
    cudaEventRecord(evJoin, s2);

    // main branch: init + place
    cudaMemsetAsync(fill_ptr, 0, (NMAX + 1) * sizeof(int), 0);
    k_place<<<(E + 255) / 256, 256>>>(ei, E);

    // join, then epilogue + aggregation
    cudaStreamWaitEvent(0, evJoin, 0);
    k_scale<<<(n * 8 + 255) / 256, 256>>>(b, out, n);

    int nb_agg = (n + 3) / 4;
    k_agg<<<nb_agg + 16, 128>>>(out, n, nb_agg);
}